// round 12
// baseline (speedup 1.0000x reference)
#include <cuda_runtime.h>

#define NNODES 50000
#define DIM    128
#define NHOPS  3
#define SIGMA_F 0.1f
#define MAXE   800000

// ---------------------------------------------------------------------------
// Scratch (__device__ globals — allocation-free rule).
// g_cnt invariant: zeroed at end of every kernel_launch (scan), and statics
// are zero-initialized at load, so hist_kernel never needs a zeroing pass.
// ---------------------------------------------------------------------------
__device__ int g_cnt[NNODES];        // in-degree histogram
__device__ int g_off[NNODES + 1];    // segment offsets (CSR by dst)
__device__ int g_cur[NNODES];        // scatter cursors
__device__ int g_src[MAXE];          // src indices sorted by dst

// ---------------------------------------------------------------------------
// Threefry-2x32 (20 rounds) — matches JAX bit-for-bit (verified R2)
// ---------------------------------------------------------------------------
__host__ __device__ __forceinline__ void tf_round(unsigned& x0, unsigned& x1, int r) {
    x0 += x1;
#ifdef __CUDA_ARCH__
    x1 = __funnelshift_l(x1, x1, r);
#else
    x1 = (x1 << r) | (x1 >> (32 - r));
#endif
    x1 ^= x0;
}

__host__ __device__ __forceinline__ void threefry2x32(
    unsigned k0, unsigned k1, unsigned x0, unsigned x1,
    unsigned& o0, unsigned& o1)
{
    unsigned k2 = k0 ^ k1 ^ 0x1BD11BDAu;
    x0 += k0; x1 += k1;
    tf_round(x0,x1,13); tf_round(x0,x1,15); tf_round(x0,x1,26); tf_round(x0,x1, 6);
    x0 += k1; x1 += k2 + 1u;
    tf_round(x0,x1,17); tf_round(x0,x1,29); tf_round(x0,x1,16); tf_round(x0,x1,24);
    x0 += k2; x1 += k0 + 2u;
    tf_round(x0,x1,13); tf_round(x0,x1,15); tf_round(x0,x1,26); tf_round(x0,x1, 6);
    x0 += k0; x1 += k1 + 3u;
    tf_round(x0,x1,17); tf_round(x0,x1,29); tf_round(x0,x1,16); tf_round(x0,x1,24);
    x0 += k1; x1 += k2 + 4u;
    tf_round(x0,x1,13); tf_round(x0,x1,15); tf_round(x0,x1,26); tf_round(x0,x1, 6);
    x0 += k2; x1 += k0 + 5u;
    o0 = x0; o1 = x1;
}

// XLA ErfInv32 polynomial (Giles)
__device__ __forceinline__ float erfinv_f(float x) {
    float w = -log1pf(-x * x);
    float p;
    if (w < 5.0f) {
        w -= 2.5f;
        p =              2.81022636e-08f;
        p = fmaf(p, w,   3.43273939e-07f);
        p = fmaf(p, w,  -3.5233877e-06f);
        p = fmaf(p, w,  -4.39150654e-06f);
        p = fmaf(p, w,   0.00021858087f);
        p = fmaf(p, w,  -0.00125372503f);
        p = fmaf(p, w,  -0.00417768164f);
        p = fmaf(p, w,   0.246640727f);
        p = fmaf(p, w,   1.50140941f);
    } else {
        w = sqrtf(w) - 3.0f;
        p =             -0.000200214257f;
        p = fmaf(p, w,   0.000100950558f);
        p = fmaf(p, w,   0.00134934322f);
        p = fmaf(p, w,  -0.00367342844f);
        p = fmaf(p, w,   0.00573950773f);
        p = fmaf(p, w,  -0.0076224613f);
        p = fmaf(p, w,   0.00943887047f);
        p = fmaf(p, w,   1.00167406f);
        p = fmaf(p, w,   2.83297682f);
    }
    return p * x;
}

__device__ __forceinline__ float jax_normal(unsigned k0, unsigned k1, unsigned idx) {
    unsigned o0, o1;
    threefry2x32(k0, k1, 0u, idx, o0, o1);
    unsigned bits = o0 ^ o1;
    float u01 = __uint_as_float((bits >> 9) | 0x3F800000u) - 1.0f;
    const float LO = -0.99999994f;          // nextafterf(-1, 0)
    float u = fmaxf(LO, u01 * 2.0f + LO);   // (1.0f - LO) rounds to exactly 2.0f
    return 1.41421356f * erfinv_f(u);       // sqrt(2) in f32
}

// ---------------------------------------------------------------------------
// edge-index dtype detection, inlined (int64 values < 50000 -> odd words zero)
// ---------------------------------------------------------------------------
__device__ __forceinline__ int detect64(const void* ei) {
    const unsigned* w = (const unsigned*)ei;
    return ((w[1] == 0u) + (w[3] == 0u) + (w[5] == 0u) + (w[7] == 0u) + (w[9] == 0u)) == 5;
}

__device__ __forceinline__ void load_edge(const void* ei, int is64, int e, int E,
                                          int& s, int& d) {
    if (is64) {
        const long long* p = (const long long*)ei;
        s = (int)__ldg(p + e);
        d = (int)__ldg(p + e + E);
    } else {
        const int* p = (const int*)ei;
        s = __ldg(p + e);
        d = __ldg(p + e + E);
    }
}

// ---------------------------------------------------------------------------
// init: h0 = normalize(x) -> out[0]. One warp per row.
// ---------------------------------------------------------------------------
__global__ __launch_bounds__(256) void init_kernel(
    const float* __restrict__ x, float* __restrict__ out0)
{
    int gt   = blockIdx.x * blockDim.x + threadIdx.x;
    int row  = gt >> 5;
    int lane = threadIdx.x & 31;
    if (row >= NNODES) return;
    float4 v = __ldg((const float4*)(x + (size_t)row * DIM) + lane);
    float ss = v.x*v.x + v.y*v.y + v.z*v.z + v.w*v.w;
#pragma unroll
    for (int o = 16; o; o >>= 1) ss += __shfl_xor_sync(0xffffffffu, ss, o);
    float inv = 1.0f / fmaxf(sqrtf(ss), 1e-12f);
    v.x *= inv; v.y *= inv; v.z *= inv; v.w *= inv;
    ((float4*)(out0 + (size_t)row * DIM))[lane] = v;
}

// ---------------------------------------------------------------------------
// counting sort by dst: histogram -> single-block scan -> scatter
// ---------------------------------------------------------------------------
__global__ __launch_bounds__(256) void hist_kernel(const void* __restrict__ ei, int E) {
    int is64 = detect64(ei);
    for (int e = blockIdx.x * blockDim.x + threadIdx.x; e < E; e += gridDim.x * blockDim.x) {
        int s, d; load_edge(ei, is64, e, E, s, d);
        atomicAdd(&g_cnt[d], 1);
    }
}

// single-block exclusive scan of g_cnt -> g_off/g_cur; re-zeros g_cnt
__global__ __launch_bounds__(1024) void scan_kernel(int E) {
    __shared__ int warpsum[32];
    int t = threadIdx.x;
    const int CH = (NNODES + 1023) / 1024;      // 49 per thread
    int beg = t * CH;
    int endi = min(beg + CH, NNODES);

    int local = 0;
    for (int i = beg; i < endi; ++i) local += g_cnt[i];

    int lane = t & 31, wid = t >> 5;
    int v = local;
#pragma unroll
    for (int o = 1; o < 32; o <<= 1) {
        int u = __shfl_up_sync(0xffffffffu, v, o);
        if (lane >= o) v += u;
    }
    if (lane == 31) warpsum[wid] = v;
    __syncthreads();
    if (wid == 0) {
        int s = warpsum[lane];
#pragma unroll
        for (int o = 1; o < 32; o <<= 1) {
            int u = __shfl_up_sync(0xffffffffu, s, o);
            if (lane >= o) s += u;
        }
        warpsum[lane] = s;
    }
    __syncthreads();

    int run = (v - local) + (wid ? warpsum[wid - 1] : 0);   // exclusive prefix
    for (int i = beg; i < endi; ++i) {
        int c = g_cnt[i];
        g_off[i] = run;
        g_cur[i] = run;
        g_cnt[i] = 0;                 // restore zeroed invariant for next call
        run += c;
    }
    if (t == 0) g_off[NNODES] = E;
}

__global__ __launch_bounds__(256) void scatter_kernel(const void* __restrict__ ei, int E) {
    int is64 = detect64(ei);
    for (int e = blockIdx.x * blockDim.x + threadIdx.x; e < E; e += gridDim.x * blockDim.x) {
        int s, d; load_edge(ei, is64, e, E, s, d);
        int pos = atomicAdd(&g_cur[d], 1);
        g_src[pos] = s;
    }
}

// ---------------------------------------------------------------------------
// fused hop: one warp per dst row, organized as 4 groups x 8 lanes.
// Group g processes edge t+g; lane l of each group owns columns
// [l*16, l*16+16) (4 float4s). Per 4 edges: 4x coalesced 128B row loads,
// ONE shared 3-level butterfly (3 SHFLs), 1 uniform idx LDG, group-parallel
// sigmoid. Cross-group acc reduction + epilogue once per row.
// ---------------------------------------------------------------------------
__global__ __launch_bounds__(256) void hop_fused_kernel(
    const float* __restrict__ h, float* __restrict__ out,
    unsigned k0, unsigned k1)
{
    int row  = (blockIdx.x * blockDim.x + threadIdx.x) >> 5;
    int lane = threadIdx.x & 31;
    if (row >= NNODES) return;

    int l = lane & 7;      // column sub-block within group
    int g = lane >> 3;     // edge group 0..3

    int start = g_off[row];
    int end   = g_off[row + 1];

    // b, acc: 4 float4s per lane = columns l*16 .. l*16+15
    const float4* brow = (const float4*)(h + (size_t)row * DIM);
    float4 b0 = __ldg(brow + l*4 + 0), b1 = __ldg(brow + l*4 + 1);
    float4 b2 = __ldg(brow + l*4 + 2), b3 = __ldg(brow + l*4 + 3);
    float4 ac0 = {0,0,0,0}, ac1 = {0,0,0,0}, ac2 = {0,0,0,0}, ac3 = {0,0,0,0};

    if (start < end) {
        // preload first edge of this group (clamped; invalid groups masked later)
        int e0 = min(start + g, end - 1);
        const float4* r = (const float4*)(h + (size_t)__ldg(g_src + e0) * DIM);
        float4 c0 = __ldg(r + l*4 + 0), c1 = __ldg(r + l*4 + 1);
        float4 c2 = __ldg(r + l*4 + 2), c3 = __ldg(r + l*4 + 3);

        for (int t = start; t < end; t += 4) {
            float4 u0 = c0, u1 = c1, u2 = c2, u3 = c3;
            bool valid = (t + g < end);

            if (t + 4 < end) {       // warp-uniform prefetch of next 4 edges
                int en = min(t + 4 + g, end - 1);
                const float4* rn = (const float4*)(h + (size_t)__ldg(g_src + en) * DIM);
                c0 = __ldg(rn + l*4 + 0); c1 = __ldg(rn + l*4 + 1);
                c2 = __ldg(rn + l*4 + 2); c3 = __ldg(rn + l*4 + 3);
            }

            float p = u0.x*b0.x + u0.y*b0.y + u0.z*b0.z + u0.w*b0.w
                    + u1.x*b1.x + u1.y*b1.y + u1.z*b1.z + u1.w*b1.w
                    + u2.x*b2.x + u2.y*b2.y + u2.z*b2.z + u2.w*b2.w
                    + u3.x*b3.x + u3.y*b3.y + u3.z*b3.z + u3.w*b3.w;
            // 3-level butterfly within each 8-lane group (all 4 groups at once)
            p += __shfl_xor_sync(0xffffffffu, p, 1);
            p += __shfl_xor_sync(0xffffffffu, p, 2);
            p += __shfl_xor_sync(0xffffffffu, p, 4);

            float alpha = valid ? __fdividef(1.0f, 1.0f + __expf(-p)) : 0.0f;
            ac0.x = fmaf(alpha, u0.x, ac0.x); ac0.y = fmaf(alpha, u0.y, ac0.y);
            ac0.z = fmaf(alpha, u0.z, ac0.z); ac0.w = fmaf(alpha, u0.w, ac0.w);
            ac1.x = fmaf(alpha, u1.x, ac1.x); ac1.y = fmaf(alpha, u1.y, ac1.y);
            ac1.z = fmaf(alpha, u1.z, ac1.z); ac1.w = fmaf(alpha, u1.w, ac1.w);
            ac2.x = fmaf(alpha, u2.x, ac2.x); ac2.y = fmaf(alpha, u2.y, ac2.y);
            ac2.z = fmaf(alpha, u2.z, ac2.z); ac2.w = fmaf(alpha, u2.w, ac2.w);
            ac3.x = fmaf(alpha, u3.x, ac3.x); ac3.y = fmaf(alpha, u3.y, ac3.y);
            ac3.z = fmaf(alpha, u3.z, ac3.z); ac3.w = fmaf(alpha, u3.w, ac3.w);
        }
    }

    // cross-group reduction of the 4 parallel accumulators (masks 8, 16)
#pragma unroll
    for (int m = 8; m <= 16; m <<= 1) {
        ac0.x += __shfl_xor_sync(0xffffffffu, ac0.x, m);
        ac0.y += __shfl_xor_sync(0xffffffffu, ac0.y, m);
        ac0.z += __shfl_xor_sync(0xffffffffu, ac0.z, m);
        ac0.w += __shfl_xor_sync(0xffffffffu, ac0.w, m);
        ac1.x += __shfl_xor_sync(0xffffffffu, ac1.x, m);
        ac1.y += __shfl_xor_sync(0xffffffffu, ac1.y, m);
        ac1.z += __shfl_xor_sync(0xffffffffu, ac1.z, m);
        ac1.w += __shfl_xor_sync(0xffffffffu, ac1.w, m);
        ac2.x += __shfl_xor_sync(0xffffffffu, ac2.x, m);
        ac2.y += __shfl_xor_sync(0xffffffffu, ac2.y, m);
        ac2.z += __shfl_xor_sync(0xffffffffu, ac2.z, m);
        ac2.w += __shfl_xor_sync(0xffffffffu, ac2.w, m);
        ac3.x += __shfl_xor_sync(0xffffffffu, ac3.x, m);
        ac3.y += __shfl_xor_sync(0xffffffffu, ac3.y, m);
        ac3.z += __shfl_xor_sync(0xffffffffu, ac3.z, m);
        ac3.w += __shfl_xor_sync(0xffffffffu, ac3.w, m);
    }

    // lane (g,l) writes float4 #(l*4+g): pick acc[g], add its noise
    float4 v = (g == 0) ? ac0 : (g == 1) ? ac1 : (g == 2) ? ac2 : ac3;
    int f4pos = l*4 + g;
    unsigned base = (unsigned)row * DIM + (unsigned)f4pos * 4;
    v.x += SIGMA_F * jax_normal(k0, k1, base + 0);
    v.y += SIGMA_F * jax_normal(k0, k1, base + 1);
    v.z += SIGMA_F * jax_normal(k0, k1, base + 2);
    v.w += SIGMA_F * jax_normal(k0, k1, base + 3);

    float ss = v.x*v.x + v.y*v.y + v.z*v.z + v.w*v.w;
#pragma unroll
    for (int o = 16; o; o >>= 1) ss += __shfl_xor_sync(0xffffffffu, ss, o);
    float inv = 1.0f / fmaxf(sqrtf(ss), 1e-12f);
    v.x *= inv; v.y *= inv; v.z *= inv; v.w *= inv;

    ((float4*)(out + (size_t)row * DIM))[f4pos] = v;
}

// ---------------------------------------------------------------------------
// launch
// ---------------------------------------------------------------------------
extern "C" void kernel_launch(void* const* d_in, const int* in_sizes, int n_in,
                              void* d_out, int out_size)
{
    int i_x = 0, i_e = 1;
    if (in_sizes[0] != NNODES * DIM) { i_x = 1; i_e = 0; }
    const float* x  = (const float*)d_in[i_x];
    const void*  ei = d_in[i_e];
    int E = in_sizes[i_e] / 2;

    float* out = (float*)d_out;

    // fold-like split of jax.random.key(1) into NHOPS subkeys (exact)
    unsigned keys[NHOPS][2];
    for (unsigned k = 0; k < NHOPS; ++k)
        threefry2x32(0u, 1u, 0u, k, keys[k][0], keys[k][1]);

    const int ROW_BLOCKS  = (NNODES * 32 + 255) / 256;
    const int EDGE_BLOCKS = (E + 255) / 256;

    init_kernel<<<ROW_BLOCKS, 256>>>(x, out);          // 1
    hist_kernel<<<EDGE_BLOCKS, 256>>>(ei, E);          // 2
    scan_kernel<<<1, 1024>>>(E);                       // 3
    scatter_kernel<<<EDGE_BLOCKS, 256>>>(ei, E);       // 4

    for (int k = 0; k < NHOPS; ++k) {                  // 5, 6, 7
        hop_fused_kernel<<<ROW_BLOCKS, 256>>>(out + (size_t)k * NNODES * DIM,
                                              out + (size_t)(k + 1) * NNODES * DIM,
                                              keys[k][0], keys[k][1]);
    }
}

// round 13
// speedup vs baseline: 1.4263x; 1.4263x over previous
#include <cuda_runtime.h>

#define NNODES 50000
#define DIM    128
#define NHOPS  3
#define SIGMA_F 0.1f
#define MAXE   800000

// ---------------------------------------------------------------------------
// Scratch (__device__ globals — allocation-free rule).
// g_cnt invariant: zeroed at end of every kernel_launch (scan), and statics
// are zero-initialized at load, so the histogram never needs a zeroing pass.
// ---------------------------------------------------------------------------
__device__ int g_cnt[NNODES];        // in-degree histogram
__device__ int g_off[NNODES + 1];    // segment offsets (CSR by dst)
__device__ int g_cur[NNODES];        // scatter cursors
__device__ int g_src[MAXE];          // src indices sorted by dst

// ---------------------------------------------------------------------------
// Threefry-2x32 (20 rounds) — matches JAX bit-for-bit (verified R2)
// ---------------------------------------------------------------------------
__host__ __device__ __forceinline__ void tf_round(unsigned& x0, unsigned& x1, int r) {
    x0 += x1;
#ifdef __CUDA_ARCH__
    x1 = __funnelshift_l(x1, x1, r);
#else
    x1 = (x1 << r) | (x1 >> (32 - r));
#endif
    x1 ^= x0;
}

__host__ __device__ __forceinline__ void threefry2x32(
    unsigned k0, unsigned k1, unsigned x0, unsigned x1,
    unsigned& o0, unsigned& o1)
{
    unsigned k2 = k0 ^ k1 ^ 0x1BD11BDAu;
    x0 += k0; x1 += k1;
    tf_round(x0,x1,13); tf_round(x0,x1,15); tf_round(x0,x1,26); tf_round(x0,x1, 6);
    x0 += k1; x1 += k2 + 1u;
    tf_round(x0,x1,17); tf_round(x0,x1,29); tf_round(x0,x1,16); tf_round(x0,x1,24);
    x0 += k2; x1 += k0 + 2u;
    tf_round(x0,x1,13); tf_round(x0,x1,15); tf_round(x0,x1,26); tf_round(x0,x1, 6);
    x0 += k0; x1 += k1 + 3u;
    tf_round(x0,x1,17); tf_round(x0,x1,29); tf_round(x0,x1,16); tf_round(x0,x1,24);
    x0 += k1; x1 += k2 + 4u;
    tf_round(x0,x1,13); tf_round(x0,x1,15); tf_round(x0,x1,26); tf_round(x0,x1, 6);
    x0 += k2; x1 += k0 + 5u;
    o0 = x0; o1 = x1;
}

// XLA ErfInv32 polynomial (Giles)
__device__ __forceinline__ float erfinv_f(float x) {
    float w = -log1pf(-x * x);
    float p;
    if (w < 5.0f) {
        w -= 2.5f;
        p =              2.81022636e-08f;
        p = fmaf(p, w,   3.43273939e-07f);
        p = fmaf(p, w,  -3.5233877e-06f);
        p = fmaf(p, w,  -4.39150654e-06f);
        p = fmaf(p, w,   0.00021858087f);
        p = fmaf(p, w,  -0.00125372503f);
        p = fmaf(p, w,  -0.00417768164f);
        p = fmaf(p, w,   0.246640727f);
        p = fmaf(p, w,   1.50140941f);
    } else {
        w = sqrtf(w) - 3.0f;
        p =             -0.000200214257f;
        p = fmaf(p, w,   0.000100950558f);
        p = fmaf(p, w,   0.00134934322f);
        p = fmaf(p, w,  -0.00367342844f);
        p = fmaf(p, w,   0.00573950773f);
        p = fmaf(p, w,  -0.0076224613f);
        p = fmaf(p, w,   0.00943887047f);
        p = fmaf(p, w,   1.00167406f);
        p = fmaf(p, w,   2.83297682f);
    }
    return p * x;
}

__device__ __forceinline__ float jax_normal(unsigned k0, unsigned k1, unsigned idx) {
    unsigned o0, o1;
    threefry2x32(k0, k1, 0u, idx, o0, o1);
    unsigned bits = o0 ^ o1;
    float u01 = __uint_as_float((bits >> 9) | 0x3F800000u) - 1.0f;
    const float LO = -0.99999994f;          // nextafterf(-1, 0)
    float u = fmaxf(LO, u01 * 2.0f + LO);   // (1.0f - LO) rounds to exactly 2.0f
    return 1.41421356f * erfinv_f(u);       // sqrt(2) in f32
}

// ---------------------------------------------------------------------------
// edge-index dtype detection, inlined (int64 values < 50000 -> odd words zero)
// ---------------------------------------------------------------------------
__device__ __forceinline__ int detect64(const void* ei) {
    const unsigned* w = (const unsigned*)ei;
    return ((w[1] == 0u) + (w[3] == 0u) + (w[5] == 0u) + (w[7] == 0u) + (w[9] == 0u)) == 5;
}

__device__ __forceinline__ void load_edge(const void* ei, int is64, int e, int E,
                                          int& s, int& d) {
    if (is64) {
        const long long* p = (const long long*)ei;
        s = (int)__ldg(p + e);
        d = (int)__ldg(p + e + E);
    } else {
        const int* p = (const int*)ei;
        s = __ldg(p + e);
        d = __ldg(p + e + E);
    }
}

__device__ __forceinline__ float4 ld_row(const float* __restrict__ h, int row, int lane) {
    return __ldg((const float4*)(h + (size_t)row * DIM) + lane);
}

// ---------------------------------------------------------------------------
// fused init + hist (independent work, one launch):
//   warp-per-row: h0 = normalize(x) -> out[0]
//   grid-stride over edges: in-degree histogram into g_cnt
// ---------------------------------------------------------------------------
__global__ __launch_bounds__(256) void init_hist_kernel(
    const float* __restrict__ x, float* __restrict__ out0,
    const void* __restrict__ ei, int E)
{
    int gt   = blockIdx.x * blockDim.x + threadIdx.x;
    int row  = gt >> 5;
    int lane = threadIdx.x & 31;

    if (row < NNODES) {
        float4 v = __ldg((const float4*)(x + (size_t)row * DIM) + lane);
        float ss = v.x*v.x + v.y*v.y + v.z*v.z + v.w*v.w;
#pragma unroll
        for (int o = 16; o; o >>= 1) ss += __shfl_xor_sync(0xffffffffu, ss, o);
        float inv = 1.0f / fmaxf(sqrtf(ss), 1e-12f);
        v.x *= inv; v.y *= inv; v.z *= inv; v.w *= inv;
        ((float4*)(out0 + (size_t)row * DIM))[lane] = v;
    }

    // histogram: grid-stride over edges (dst only)
    int is64 = detect64(ei);
    int stride = gridDim.x * blockDim.x;
    for (int e = gt; e < E; e += stride) {
        int d;
        if (is64) d = (int)__ldg((const long long*)ei + e + E);
        else      d = __ldg((const int*)ei + e + E);
        atomicAdd(&g_cnt[d], 1);
    }
}

// ---------------------------------------------------------------------------
// single-block exclusive scan of g_cnt -> g_off/g_cur; re-zeros g_cnt
// ---------------------------------------------------------------------------
__global__ __launch_bounds__(1024) void scan_kernel(int E) {
    __shared__ int warpsum[32];
    int t = threadIdx.x;
    const int CH = (NNODES + 1023) / 1024;      // 49 per thread
    int beg = t * CH;
    int endi = min(beg + CH, NNODES);

    int local = 0;
    for (int i = beg; i < endi; ++i) local += g_cnt[i];

    int lane = t & 31, wid = t >> 5;
    int v = local;
#pragma unroll
    for (int o = 1; o < 32; o <<= 1) {
        int u = __shfl_up_sync(0xffffffffu, v, o);
        if (lane >= o) v += u;
    }
    if (lane == 31) warpsum[wid] = v;
    __syncthreads();
    if (wid == 0) {
        int s = warpsum[lane];
#pragma unroll
        for (int o = 1; o < 32; o <<= 1) {
            int u = __shfl_up_sync(0xffffffffu, s, o);
            if (lane >= o) s += u;
        }
        warpsum[lane] = s;
    }
    __syncthreads();

    int run = (v - local) + (wid ? warpsum[wid - 1] : 0);   // exclusive prefix
    for (int i = beg; i < endi; ++i) {
        int c = g_cnt[i];
        g_off[i] = run;
        g_cur[i] = run;
        g_cnt[i] = 0;                 // restore zeroed invariant for next call
        run += c;
    }
    if (t == 0) g_off[NNODES] = E;
}

__global__ __launch_bounds__(256) void scatter_kernel(const void* __restrict__ ei, int E) {
    int is64 = detect64(ei);
    for (int e = blockIdx.x * blockDim.x + threadIdx.x; e < E; e += gridDim.x * blockDim.x) {
        int s, d; load_edge(ei, is64, e, E, s, d);
        int pos = atomicAdd(&g_cur[d], 1);
        g_src[pos] = s;
    }
}

// ---------------------------------------------------------------------------
// fused hop (EXACT R3 structure — proven best): one warp per dst node,
// register segment-sum over sorted in-edges, 1-deep gather pipeline,
// then noise + normalize + store.
// ---------------------------------------------------------------------------
__global__ __launch_bounds__(256) void hop_fused_kernel(
    const float* __restrict__ h, float* __restrict__ out,
    unsigned k0, unsigned k1)
{
    int row  = (blockIdx.x * blockDim.x + threadIdx.x) >> 5;
    int lane = threadIdx.x & 31;
    if (row >= NNODES) return;

    int start = g_off[row];
    int end   = g_off[row + 1];

    float4 b = ld_row(h, row, lane);
    float4 acc = make_float4(0.f, 0.f, 0.f, 0.f);

    for (int j0 = start; j0 < end; j0 += 32) {
        int n = min(32, end - j0);
        int idx = (lane < n) ? __ldg(g_src + j0 + lane) : 0;

        // 1-deep software pipeline on the gather
        int s0 = __shfl_sync(0xffffffffu, idx, 0);
        float4 a = ld_row(h, s0, lane);
        for (int t = 0; t < n; ++t) {
            float4 cur = a;
            if (t + 1 < n) {
                int sn = __shfl_sync(0xffffffffu, idx, t + 1);
                a = ld_row(h, sn, lane);
            }
            float dot = cur.x*b.x + cur.y*b.y + cur.z*b.z + cur.w*b.w;
#pragma unroll
            for (int o = 16; o; o >>= 1) dot += __shfl_xor_sync(0xffffffffu, dot, o);
            float alpha = __fdividef(1.0f, 1.0f + __expf(-dot));
            acc.x = fmaf(alpha, cur.x, acc.x);
            acc.y = fmaf(alpha, cur.y, acc.y);
            acc.z = fmaf(alpha, cur.z, acc.z);
            acc.w = fmaf(alpha, cur.w, acc.w);
        }
    }

    unsigned base = (unsigned)row * DIM + (unsigned)lane * 4;
    acc.x += SIGMA_F * jax_normal(k0, k1, base + 0);
    acc.y += SIGMA_F * jax_normal(k0, k1, base + 1);
    acc.z += SIGMA_F * jax_normal(k0, k1, base + 2);
    acc.w += SIGMA_F * jax_normal(k0, k1, base + 3);

    float ss = acc.x*acc.x + acc.y*acc.y + acc.z*acc.z + acc.w*acc.w;
#pragma unroll
    for (int o = 16; o; o >>= 1) ss += __shfl_xor_sync(0xffffffffu, ss, o);
    float inv = 1.0f / fmaxf(sqrtf(ss), 1e-12f);
    acc.x *= inv; acc.y *= inv; acc.z *= inv; acc.w *= inv;

    ((float4*)(out + (size_t)row * DIM))[lane] = acc;
}

// ---------------------------------------------------------------------------
// launch: 6 launches total; hop3 is #6 so ncu (-s 5 -c 1) profiles a hop
// ---------------------------------------------------------------------------
extern "C" void kernel_launch(void* const* d_in, const int* in_sizes, int n_in,
                              void* d_out, int out_size)
{
    int i_x = 0, i_e = 1;
    if (in_sizes[0] != NNODES * DIM) { i_x = 1; i_e = 0; }
    const float* x  = (const float*)d_in[i_x];
    const void*  ei = d_in[i_e];
    int E = in_sizes[i_e] / 2;

    float* out = (float*)d_out;

    // fold-like split of jax.random.key(1) into NHOPS subkeys (exact)
    unsigned keys[NHOPS][2];
    for (unsigned k = 0; k < NHOPS; ++k)
        threefry2x32(0u, 1u, 0u, k, keys[k][0], keys[k][1]);

    const int ROW_BLOCKS = (NNODES * 32 + 255) / 256;

    init_hist_kernel<<<ROW_BLOCKS, 256>>>(x, out, ei, E);   // 1
    scan_kernel<<<1, 1024>>>(E);                            // 2
    scatter_kernel<<<(E + 255) / 256, 256>>>(ei, E);        // 3

    for (int k = 0; k < NHOPS; ++k) {                       // 4, 5, 6
        hop_fused_kernel<<<ROW_BLOCKS, 256>>>(out + (size_t)k * NNODES * DIM,
                                              out + (size_t)(k + 1) * NNODES * DIM,
                                              keys[k][0], keys[k][1]);
    }
}

// round 14
// speedup vs baseline: 1.5671x; 1.0987x over previous
#include <cuda_runtime.h>

#define NNODES 50000
#define DIM    128
#define NHOPS  3
#define SIGMA_F 0.1f
#define MAXE   800000

// ---------------------------------------------------------------------------
// Scratch (__device__ globals — allocation-free rule).
// g_cnt invariant: zeroed at end of every kernel_launch (scan), and statics
// are zero-initialized at load, so the histogram never needs a zeroing pass.
// ---------------------------------------------------------------------------
__device__ int g_cnt[NNODES];        // in-degree histogram
__device__ int g_off[NNODES + 1];    // segment offsets (CSR by dst)
__device__ int g_cur[NNODES];        // scatter cursors
__device__ int g_src[MAXE];          // src indices sorted by dst

// ---------------------------------------------------------------------------
// Threefry-2x32 (20 rounds) — matches JAX bit-for-bit (verified R2)
// ---------------------------------------------------------------------------
__host__ __device__ __forceinline__ void tf_round(unsigned& x0, unsigned& x1, int r) {
    x0 += x1;
#ifdef __CUDA_ARCH__
    x1 = __funnelshift_l(x1, x1, r);
#else
    x1 = (x1 << r) | (x1 >> (32 - r));
#endif
    x1 ^= x0;
}

__host__ __device__ __forceinline__ void threefry2x32(
    unsigned k0, unsigned k1, unsigned x0, unsigned x1,
    unsigned& o0, unsigned& o1)
{
    unsigned k2 = k0 ^ k1 ^ 0x1BD11BDAu;
    x0 += k0; x1 += k1;
    tf_round(x0,x1,13); tf_round(x0,x1,15); tf_round(x0,x1,26); tf_round(x0,x1, 6);
    x0 += k1; x1 += k2 + 1u;
    tf_round(x0,x1,17); tf_round(x0,x1,29); tf_round(x0,x1,16); tf_round(x0,x1,24);
    x0 += k2; x1 += k0 + 2u;
    tf_round(x0,x1,13); tf_round(x0,x1,15); tf_round(x0,x1,26); tf_round(x0,x1, 6);
    x0 += k0; x1 += k1 + 3u;
    tf_round(x0,x1,17); tf_round(x0,x1,29); tf_round(x0,x1,16); tf_round(x0,x1,24);
    x0 += k1; x1 += k2 + 4u;
    tf_round(x0,x1,13); tf_round(x0,x1,15); tf_round(x0,x1,26); tf_round(x0,x1, 6);
    x0 += k2; x1 += k0 + 5u;
    o0 = x0; o1 = x1;
}

// XLA ErfInv32 polynomial (Giles)
__device__ __forceinline__ float erfinv_f(float x) {
    float w = -log1pf(-x * x);
    float p;
    if (w < 5.0f) {
        w -= 2.5f;
        p =              2.81022636e-08f;
        p = fmaf(p, w,   3.43273939e-07f);
        p = fmaf(p, w,  -3.5233877e-06f);
        p = fmaf(p, w,  -4.39150654e-06f);
        p = fmaf(p, w,   0.00021858087f);
        p = fmaf(p, w,  -0.00125372503f);
        p = fmaf(p, w,  -0.00417768164f);
        p = fmaf(p, w,   0.246640727f);
        p = fmaf(p, w,   1.50140941f);
    } else {
        w = sqrtf(w) - 3.0f;
        p =             -0.000200214257f;
        p = fmaf(p, w,   0.000100950558f);
        p = fmaf(p, w,   0.00134934322f);
        p = fmaf(p, w,  -0.00367342844f);
        p = fmaf(p, w,   0.00573950773f);
        p = fmaf(p, w,  -0.0076224613f);
        p = fmaf(p, w,   0.00943887047f);
        p = fmaf(p, w,   1.00167406f);
        p = fmaf(p, w,   2.83297682f);
    }
    return p * x;
}

__device__ __forceinline__ float jax_normal(unsigned k0, unsigned k1, unsigned idx) {
    unsigned o0, o1;
    threefry2x32(k0, k1, 0u, idx, o0, o1);
    unsigned bits = o0 ^ o1;
    float u01 = __uint_as_float((bits >> 9) | 0x3F800000u) - 1.0f;
    const float LO = -0.99999994f;          // nextafterf(-1, 0)
    float u = fmaxf(LO, u01 * 2.0f + LO);   // (1.0f - LO) rounds to exactly 2.0f
    return 1.41421356f * erfinv_f(u);       // sqrt(2) in f32
}

// ---------------------------------------------------------------------------
// edge-index dtype detection, inlined (int64 values < 50000 -> odd words zero)
// ---------------------------------------------------------------------------
__device__ __forceinline__ int detect64(const void* ei) {
    const unsigned* w = (const unsigned*)ei;
    return ((w[1] == 0u) + (w[3] == 0u) + (w[5] == 0u) + (w[7] == 0u) + (w[9] == 0u)) == 5;
}

__device__ __forceinline__ void load_edge(const void* ei, int is64, int e, int E,
                                          int& s, int& d) {
    if (is64) {
        const long long* p = (const long long*)ei;
        s = (int)__ldg(p + e);
        d = (int)__ldg(p + e + E);
    } else {
        const int* p = (const int*)ei;
        s = __ldg(p + e);
        d = __ldg(p + e + E);
    }
}

__device__ __forceinline__ float4 ld_row(const float* __restrict__ h, int row, int lane) {
    return __ldg((const float4*)(h + (size_t)row * DIM) + lane);
}

// ---------------------------------------------------------------------------
// fused init + hist (independent work, one launch)
// ---------------------------------------------------------------------------
__global__ __launch_bounds__(256) void init_hist_kernel(
    const float* __restrict__ x, float* __restrict__ out0,
    const void* __restrict__ ei, int E)
{
    int gt   = blockIdx.x * blockDim.x + threadIdx.x;
    int row  = gt >> 5;
    int lane = threadIdx.x & 31;

    if (row < NNODES) {
        float4 v = __ldg((const float4*)(x + (size_t)row * DIM) + lane);
        float ss = v.x*v.x + v.y*v.y + v.z*v.z + v.w*v.w;
#pragma unroll
        for (int o = 16; o; o >>= 1) ss += __shfl_xor_sync(0xffffffffu, ss, o);
        float inv = 1.0f / fmaxf(sqrtf(ss), 1e-12f);
        v.x *= inv; v.y *= inv; v.z *= inv; v.w *= inv;
        ((float4*)(out0 + (size_t)row * DIM))[lane] = v;
    }

    int is64 = detect64(ei);
    int stride = gridDim.x * blockDim.x;
    for (int e = gt; e < E; e += stride) {
        int d;
        if (is64) d = (int)__ldg((const long long*)ei + e + E);
        else      d = __ldg((const int*)ei + e + E);
        atomicAdd(&g_cnt[d], 1);
    }
}

// ---------------------------------------------------------------------------
// single-block exclusive scan of g_cnt -> g_off/g_cur; re-zeros g_cnt
// ---------------------------------------------------------------------------
__global__ __launch_bounds__(1024) void scan_kernel(int E) {
    __shared__ int warpsum[32];
    int t = threadIdx.x;
    const int CH = (NNODES + 1023) / 1024;      // 49 per thread
    int beg = t * CH;
    int endi = min(beg + CH, NNODES);

    int local = 0;
    for (int i = beg; i < endi; ++i) local += g_cnt[i];

    int lane = t & 31, wid = t >> 5;
    int v = local;
#pragma unroll
    for (int o = 1; o < 32; o <<= 1) {
        int u = __shfl_up_sync(0xffffffffu, v, o);
        if (lane >= o) v += u;
    }
    if (lane == 31) warpsum[wid] = v;
    __syncthreads();
    if (wid == 0) {
        int s = warpsum[lane];
#pragma unroll
        for (int o = 1; o < 32; o <<= 1) {
            int u = __shfl_up_sync(0xffffffffu, s, o);
            if (lane >= o) s += u;
        }
        warpsum[lane] = s;
    }
    __syncthreads();

    int run = (v - local) + (wid ? warpsum[wid - 1] : 0);   // exclusive prefix
    for (int i = beg; i < endi; ++i) {
        int c = g_cnt[i];
        g_off[i] = run;
        g_cur[i] = run;
        g_cnt[i] = 0;                 // restore zeroed invariant for next call
        run += c;
    }
    if (t == 0) g_off[NNODES] = E;
}

__global__ __launch_bounds__(256) void scatter_kernel(const void* __restrict__ ei, int E) {
    int is64 = detect64(ei);
    for (int e = blockIdx.x * blockDim.x + threadIdx.x; e < E; e += gridDim.x * blockDim.x) {
        int s, d; load_edge(ei, is64, e, E, s, d);
        int pos = atomicAdd(&g_cur[d], 1);
        g_src[pos] = s;
    }
}

// ---------------------------------------------------------------------------
// fused hop: one warp per dst node. 4 edges per iteration with a SHARED
// multi-value butterfly (9 SHFLs reduce 4 dots; sigmoid amortized 4x).
// Quarter q of the warp ends up holding the full dot of edge slot
// [0,2,1,3][q]; 4 broadcast SHFLs return the alphas to all lanes.
// Invalid tail slots read row 0 (idx=0, L1-hot) and are killed via alpha=0.
// No software prefetch: issue-bound kernel, scoreboard stalls absorbed by occupancy.
// ---------------------------------------------------------------------------
__global__ __launch_bounds__(256) void hop_fused_kernel(
    const float* __restrict__ h, float* __restrict__ out,
    unsigned k0, unsigned k1)
{
    int row  = (blockIdx.x * blockDim.x + threadIdx.x) >> 5;
    int lane = threadIdx.x & 31;
    if (row >= NNODES) return;

    int start = g_off[row];
    int end   = g_off[row + 1];

    // lane-constant helpers (hoisted out of all loops)
    int  l7      = lane & 7;
    int  q       = lane >> 3;                       // quarter 0..3
    int  myslot  = ((q & 1) << 1) | (q >> 1);       // bit-swap: quarter -> edge slot
    bool lo16    = lane < 16;

    float4 b = ld_row(h, row, lane);
    float4 acc = make_float4(0.f, 0.f, 0.f, 0.f);

    for (int j0 = start; j0 < end; j0 += 32) {
        int n = min(32, end - j0);
        int idx = (lane < n) ? __ldg(g_src + j0 + lane) : 0;

        for (int t = 0; t < n; t += 4) {
            int i0 = __shfl_sync(0xffffffffu, idx, t);
            int i1 = __shfl_sync(0xffffffffu, idx, (t + 1) & 31);
            int i2 = __shfl_sync(0xffffffffu, idx, (t + 2) & 31);
            int i3 = __shfl_sync(0xffffffffu, idx, (t + 3) & 31);

            float4 c0 = ld_row(h, i0, lane);
            float4 c1 = ld_row(h, i1, lane);
            float4 c2 = ld_row(h, i2, lane);
            float4 c3 = ld_row(h, i3, lane);

            float p0 = c0.x*b.x + c0.y*b.y + c0.z*b.z + c0.w*b.w;
            float p1 = c1.x*b.x + c1.y*b.y + c1.z*b.z + c1.w*b.w;
            float p2 = c2.x*b.x + c2.y*b.y + c2.z*b.z + c2.w*b.w;
            float p3 = c3.x*b.x + c3.y*b.y + c3.z*b.z + c3.w*b.w;

            // shared butterfly: xor16 on all 4, fold to 2, xor8, fold to 1, xor4/2/1
            p0 += __shfl_xor_sync(0xffffffffu, p0, 16);
            p1 += __shfl_xor_sync(0xffffffffu, p1, 16);
            p2 += __shfl_xor_sync(0xffffffffu, p2, 16);
            p3 += __shfl_xor_sync(0xffffffffu, p3, 16);
            float A = lo16 ? p0 : p1;               // halves: {e0, e1}
            float B = lo16 ? p2 : p3;               // halves: {e2, e3}
            A += __shfl_xor_sync(0xffffffffu, A, 8);
            B += __shfl_xor_sync(0xffffffffu, B, 8);
            float z = ((lane & 8) == 0) ? A : B;    // quarters: {e0, e2, e1, e3}
            z += __shfl_xor_sync(0xffffffffu, z, 4);
            z += __shfl_xor_sync(0xffffffffu, z, 2);
            z += __shfl_xor_sync(0xffffffffu, z, 1);

            // one sigmoid per lane covers this quarter's edge; mask invalid slots
            float a = __fdividef(1.0f, 1.0f + __expf(-z));
            float alpha = (t + myslot < n) ? a : 0.0f;

            // broadcast each edge's alpha from its quarter (e0<-q0, e1<-q2, e2<-q1, e3<-q3)
            float al0 = __shfl_sync(0xffffffffu, alpha, l7);
            float al1 = __shfl_sync(0xffffffffu, alpha, l7 + 16);
            float al2 = __shfl_sync(0xffffffffu, alpha, l7 + 8);
            float al3 = __shfl_sync(0xffffffffu, alpha, l7 + 24);

            acc.x = fmaf(al0, c0.x, acc.x); acc.y = fmaf(al0, c0.y, acc.y);
            acc.z = fmaf(al0, c0.z, acc.z); acc.w = fmaf(al0, c0.w, acc.w);
            acc.x = fmaf(al1, c1.x, acc.x); acc.y = fmaf(al1, c1.y, acc.y);
            acc.z = fmaf(al1, c1.z, acc.z); acc.w = fmaf(al1, c1.w, acc.w);
            acc.x = fmaf(al2, c2.x, acc.x); acc.y = fmaf(al2, c2.y, acc.y);
            acc.z = fmaf(al2, c2.z, acc.z); acc.w = fmaf(al2, c2.w, acc.w);
            acc.x = fmaf(al3, c3.x, acc.x); acc.y = fmaf(al3, c3.y, acc.y);
            acc.z = fmaf(al3, c3.z, acc.z); acc.w = fmaf(al3, c3.w, acc.w);
        }
    }

    unsigned base = (unsigned)row * DIM + (unsigned)lane * 4;
    acc.x += SIGMA_F * jax_normal(k0, k1, base + 0);
    acc.y += SIGMA_F * jax_normal(k0, k1, base + 1);
    acc.z += SIGMA_F * jax_normal(k0, k1, base + 2);
    acc.w += SIGMA_F * jax_normal(k0, k1, base + 3);

    float ss = acc.x*acc.x + acc.y*acc.y + acc.z*acc.z + acc.w*acc.w;
#pragma unroll
    for (int o = 16; o; o >>= 1) ss += __shfl_xor_sync(0xffffffffu, ss, o);
    float inv = 1.0f / fmaxf(sqrtf(ss), 1e-12f);
    acc.x *= inv; acc.y *= inv; acc.z *= inv; acc.w *= inv;

    ((float4*)(out + (size_t)row * DIM))[lane] = acc;
}

// ---------------------------------------------------------------------------
// launch: 6 launches total; hop3 is #6 so ncu (-s 5 -c 1) profiles a hop
// ---------------------------------------------------------------------------
extern "C" void kernel_launch(void* const* d_in, const int* in_sizes, int n_in,
                              void* d_out, int out_size)
{
    int i_x = 0, i_e = 1;
    if (in_sizes[0] != NNODES * DIM) { i_x = 1; i_e = 0; }
    const float* x  = (const float*)d_in[i_x];
    const void*  ei = d_in[i_e];
    int E = in_sizes[i_e] / 2;

    float* out = (float*)d_out;

    // fold-like split of jax.random.key(1) into NHOPS subkeys (exact)
    unsigned keys[NHOPS][2];
    for (unsigned k = 0; k < NHOPS; ++k)
        threefry2x32(0u, 1u, 0u, k, keys[k][0], keys[k][1]);

    const int ROW_BLOCKS = (NNODES * 32 + 255) / 256;

    init_hist_kernel<<<ROW_BLOCKS, 256>>>(x, out, ei, E);   // 1
    scan_kernel<<<1, 1024>>>(E);                            // 2
    scatter_kernel<<<(E + 255) / 256, 256>>>(ei, E);        // 3

    for (int k = 0; k < NHOPS; ++k) {                       // 4, 5, 6
        hop_fused_kernel<<<ROW_BLOCKS, 256>>>(out + (size_t)k * NNODES * DIM,
                                              out + (size_t)(k + 1) * NNODES * DIM,
                                              keys[k][0], keys[k][1]);
    }
}